// round 1
// baseline (speedup 1.0000x reference)
#include <cuda_runtime.h>
#include <cstdint>

// FeatureDictionary: fused codebook gather + barycentric interp + normal.
// Inputs (metadata order):
//  0 coords    [B,S,3]   f32
//  1 idx       [B]       i32
//  2 smpl_F    [13776,3] i32
//  3 fid       [B,S]     i32
//  4 weights   [B,S,3]   f32
//  5 sdf       [B,S,1]   f32
//  6 hitpt     [B,S,3]   f32
//  7 codebooks [256,6890,64] f32
// Output: concat( weighted_feats [B,S,64], coords_feats [B,S,3], normal [B,S,3] )

#define NUM_VERTICES 6890
#define DFEAT 64

__global__ __launch_bounds__(256)
void feature_dict_kernel(const float* __restrict__ coords,
                         const int*   __restrict__ idx,
                         const int*   __restrict__ smpl_F,
                         const int*   __restrict__ fid,
                         const float* __restrict__ weights,
                         const float* __restrict__ sdf,
                         const float* __restrict__ hitpt,
                         const float* __restrict__ codebooks,
                         float*       __restrict__ out,
                         int BS, int S)
{
    long long tid = (long long)blockIdx.x * blockDim.x + threadIdx.x;
    int p    = (int)(tid >> 4);   // point index
    int lane = (int)(tid & 15);   // feature group: 4 floats each
    if (p >= BS) return;

    int b    = p / S;
    int subj = __ldg(idx + b);
    const float* cb = codebooks + (size_t)subj * (NUM_VERTICES * DFEAT);

    int f  = __ldg(fid + p);
    int v0 = __ldg(smpl_F + 3 * f + 0);
    int v1 = __ldg(smpl_F + 3 * f + 1);
    int v2 = __ldg(smpl_F + 3 * f + 2);

    float w0 = __ldg(weights + 3 * p + 0);
    float w1 = __ldg(weights + 3 * p + 1);
    float w2 = __ldg(weights + 3 * p + 2);

    // 256B codebook rows, float4-aligned.
    const float4* r0 = (const float4*)(cb + (size_t)v0 * DFEAT);
    const float4* r1 = (const float4*)(cb + (size_t)v1 * DFEAT);
    const float4* r2 = (const float4*)(cb + (size_t)v2 * DFEAT);

    float4 a = __ldg(r0 + lane);
    float4 c = __ldg(r1 + lane);
    float4 d = __ldg(r2 + lane);

    float4 o;
    o.x = w0 * a.x + w1 * c.x + w2 * d.x;
    o.y = w0 * a.y + w1 * c.y + w2 * d.y;
    o.z = w0 * a.z + w1 * c.z + w2 * d.z;
    o.w = w0 * a.w + w1 * c.w + w2 * d.w;

    // weighted_feats at offset 0
    ((float4*)out)[(size_t)p * (DFEAT / 4) + lane] = o;

    if (lane == 0) {
        size_t C_OFF = (size_t)BS * DFEAT;           // coords_feats
        size_t N_OFF = C_OFF + (size_t)BS * 3;       // normal

        float cx = __ldg(coords + 3 * p + 0);
        float cy = __ldg(coords + 3 * p + 1);
        float cz = __ldg(coords + 3 * p + 2);
        float hx = __ldg(hitpt  + 3 * p + 0);
        float hy = __ldg(hitpt  + 3 * p + 1);
        float hz = __ldg(hitpt  + 3 * p + 2);

        float dx = hx - cx, dy = hy - cy, dz = hz - cz;
        float nrm = sqrtf(dx * dx + dy * dy + dz * dz);
        float inv = 1.0f / fmaxf(nrm, 1e-6f);

        out[N_OFF + 3 * (size_t)p + 0] = dx * inv;
        out[N_OFF + 3 * (size_t)p + 1] = dy * inv;
        out[N_OFF + 3 * (size_t)p + 2] = dz * inv;

        out[C_OFF + 3 * (size_t)p + 0] = w1;
        out[C_OFF + 3 * (size_t)p + 1] = w2;
        out[C_OFF + 3 * (size_t)p + 2] = __ldg(sdf + p);
    }
}

extern "C" void kernel_launch(void* const* d_in, const int* in_sizes, int n_in,
                              void* d_out, int out_size)
{
    const float* coords    = (const float*)d_in[0];
    const int*   idx       = (const int*)  d_in[1];
    const int*   smpl_F    = (const int*)  d_in[2];
    const int*   fid       = (const int*)  d_in[3];
    const float* weights   = (const float*)d_in[4];
    const float* sdf       = (const float*)d_in[5];
    const float* hitpt     = (const float*)d_in[6];
    const float* codebooks = (const float*)d_in[7];
    float*       out       = (float*)d_out;

    int BS = in_sizes[3];       // B*S
    int B  = in_sizes[1];       // batch
    int S  = BS / B;

    long long total = (long long)BS * 16;   // 16 lanes per point
    int threads = 256;
    long long blocks = (total + threads - 1) / threads;

    feature_dict_kernel<<<(unsigned)blocks, threads>>>(
        coords, idx, smpl_F, fid, weights, sdf, hitpt, codebooks,
        out, BS, S);
}

// round 2
// speedup vs baseline: 1.8089x; 1.8089x over previous
#include <cuda_runtime.h>
#include <cstdint>

// FeatureDictionary: fused codebook gather + barycentric interp + normal.
// Inputs (metadata order):
//  0 coords    [B,S,3]   f32
//  1 idx       [B]       i32
//  2 smpl_F    [13776,3] i32
//  3 fid       [B,S]     i32
//  4 weights   [B,S,3]   f32
//  5 sdf       [B,S,1]   f32
//  6 hitpt     [B,S,3]   f32
//  7 codebooks [256,6890,64] f32
// Output: concat( weighted_feats [B,S,64], coords_feats [B,S,3], normal [B,S,3] )

#define NUM_VERTICES 6890
#define DFEAT 64

__global__ __launch_bounds__(256)
void feature_dict_kernel(const float* __restrict__ coords,
                         const int*   __restrict__ idx,
                         const int*   __restrict__ smpl_F,
                         const int*   __restrict__ fid,
                         const float* __restrict__ weights,
                         const float* __restrict__ sdf,
                         const float* __restrict__ hitpt,
                         const float* __restrict__ codebooks,
                         float*       __restrict__ out,
                         int BS, int S)
{
    // 8 lanes per point; blockIdx.y = batch index (no integer division).
    int t   = blockIdx.x * blockDim.x + threadIdx.x;
    int ps  = t >> 3;            // point index within batch row
    int lane = t & 7;            // 2 float4 feature chunks per lane
    if (ps >= S) return;

    int b = blockIdx.y;
    int p = b * S + ps;          // global point index

    // Subject codebook base: uniform per block.
    int subj = __ldg(idx + b);
    const float* cb = codebooks + (size_t)subj * (NUM_VERTICES * DFEAT);

    int f  = __ldg(fid + p);
    int v0 = __ldg(smpl_F + 3 * f + 0);
    int v1 = __ldg(smpl_F + 3 * f + 1);
    int v2 = __ldg(smpl_F + 3 * f + 2);

    float w0 = __ldg(weights + 3 * p + 0);
    float w1 = __ldg(weights + 3 * p + 1);
    float w2 = __ldg(weights + 3 * p + 2);

    // 256B codebook rows, float4-aligned. Each lane loads chunks lane, lane+8.
    const float4* r0 = (const float4*)(cb + (size_t)v0 * DFEAT);
    const float4* r1 = (const float4*)(cb + (size_t)v1 * DFEAT);
    const float4* r2 = (const float4*)(cb + (size_t)v2 * DFEAT);

    // 6 independent loads in flight.
    float4 a0 = __ldg(r0 + lane);
    float4 c0 = __ldg(r1 + lane);
    float4 d0 = __ldg(r2 + lane);
    float4 a1 = __ldg(r0 + lane + 8);
    float4 c1 = __ldg(r1 + lane + 8);
    float4 d1 = __ldg(r2 + lane + 8);

    float4 o0, o1;
    o0.x = w0 * a0.x + w1 * c0.x + w2 * d0.x;
    o0.y = w0 * a0.y + w1 * c0.y + w2 * d0.y;
    o0.z = w0 * a0.z + w1 * c0.z + w2 * d0.z;
    o0.w = w0 * a0.w + w1 * c0.w + w2 * d0.w;
    o1.x = w0 * a1.x + w1 * c1.x + w2 * d1.x;
    o1.y = w0 * a1.y + w1 * c1.y + w2 * d1.y;
    o1.z = w0 * a1.z + w1 * c1.z + w2 * d1.z;
    o1.w = w0 * a1.w + w1 * c1.w + w2 * d1.w;

    float4* outv = (float4*)out + (size_t)p * (DFEAT / 4);
    outv[lane]     = o0;
    outv[lane + 8] = o1;

    if (lane == 0) {
        // normal
        size_t C_OFF = (size_t)BS * DFEAT;
        size_t N_OFF = C_OFF + (size_t)BS * 3;
        float cx = __ldg(coords + 3 * p + 0);
        float cy = __ldg(coords + 3 * p + 1);
        float cz = __ldg(coords + 3 * p + 2);
        float hx = __ldg(hitpt  + 3 * p + 0);
        float hy = __ldg(hitpt  + 3 * p + 1);
        float hz = __ldg(hitpt  + 3 * p + 2);
        float dx = hx - cx, dy = hy - cy, dz = hz - cz;
        float nrm = sqrtf(dx * dx + dy * dy + dz * dz);
        float inv = 1.0f / fmaxf(nrm, 1e-6f);
        out[N_OFF + 3 * (size_t)p + 0] = dx * inv;
        out[N_OFF + 3 * (size_t)p + 1] = dy * inv;
        out[N_OFF + 3 * (size_t)p + 2] = dz * inv;
    } else if (lane == 1) {
        // coords_feats = [w1, w2, sdf]
        size_t C_OFF = (size_t)BS * DFEAT;
        out[C_OFF + 3 * (size_t)p + 0] = w1;
        out[C_OFF + 3 * (size_t)p + 1] = w2;
        out[C_OFF + 3 * (size_t)p + 2] = __ldg(sdf + p);
    }
}

extern "C" void kernel_launch(void* const* d_in, const int* in_sizes, int n_in,
                              void* d_out, int out_size)
{
    const float* coords    = (const float*)d_in[0];
    const int*   idx       = (const int*)  d_in[1];
    const int*   smpl_F    = (const int*)  d_in[2];
    const int*   fid       = (const int*)  d_in[3];
    const float* weights   = (const float*)d_in[4];
    const float* sdf       = (const float*)d_in[5];
    const float* hitpt     = (const float*)d_in[6];
    const float* codebooks = (const float*)d_in[7];
    float*       out       = (float*)d_out;

    int BS = in_sizes[3];       // B*S
    int B  = in_sizes[1];       // batch
    int S  = BS / B;

    int threads = 256;
    dim3 grid((S * 8 + threads - 1) / threads, B);

    feature_dict_kernel<<<grid, threads>>>(
        coords, idx, smpl_F, fid, weights, sdf, hitpt, codebooks,
        out, BS, S);
}